// round 13
// baseline (speedup 1.0000x reference)
#include <cuda_runtime.h>

#define MEM_M 131072
#define E 512
#define CHROWS 4
#define NCHUNK (MEM_M / CHROWS)
#define PPARTS 32   // partial chunks per matrix in k_prep

typedef unsigned long long u64;

// ---- device scratch (no allocation allowed) ----
__device__ __align__(16) float g_kpart[3 * PPARTS * E];  // key GEMV partials
__device__ __align__(16) float g_wkey[E];                // unnormalized w_key
__device__ __align__(16) float g_rkey[E];                // unnormalized r_key
__device__ __align__(16) float g_erase[E];
__device__ __align__(16) float g_accA[E];                // sum sims_r * mem
__device__ __align__(16) float g_accB[E];                // sum sims_r * sims_w * mem
__device__ float g_S[2];                                 // S_r, S_w
__device__ unsigned g_next;                              // work-stealing counter
__device__ unsigned g_done;                              // k_prep completion ticket

// ---- packed f32x2 helpers (sm_103a native FFMA2) ----
__device__ __forceinline__ u64 pk2(float lo, float hi) {
    u64 r; asm("mov.b64 %0, {%1, %2};" : "=l"(r) : "f"(lo), "f"(hi)); return r;
}
__device__ __forceinline__ float hadd2(u64 v) {
    float lo, hi; asm("mov.b64 {%0, %1}, %2;" : "=f"(lo), "=f"(hi) : "l"(v));
    return lo + hi;
}
__device__ __forceinline__ u64 fma2(u64 a, u64 b, u64 c) {
    u64 r; asm("fma.rn.f32x2 %0, %1, %2, %3;" : "=l"(r) : "l"(a), "l"(b), "l"(c));
    return r;
}

// ============================================================
// K1 k_prep: key GEMVs with in-kernel final reduction.
// blocks 0..95: m = b>>5 (0=w,1=r,2=erase), p = b&31 (16 rows),
//   512 threads, 16 independent loads each (MLP=16).
// block 96: zeroes accumulators/counters/out.
// LAST GEMV block to finish (fence+ticket) reduces the 32
// partials per matrix into g_wkey/g_rkey/g_erase (L2-hot).
// Keys stay UNNORMALIZED: 1/||key|| cancels in sims/sum(sims).
// ============================================================
__global__ void k_prep(const float* __restrict__ x,
                       const float* __restrict__ wkg,
                       const float* __restrict__ weg,
                       const float* __restrict__ rkg,
                       float* __restrict__ out) {
    const int b = blockIdx.x, j = threadIdx.x;
    if (b == 96) {
        g_accA[j] = 0.f;
        g_accB[j] = 0.f;
        out[j] = 0.f;
        if (j < 2) g_S[j] = 0.f;
        if (j == 0) g_next = 0u;
        return;
    }
    const int m = b >> 5, p = b & 31;
    const float* W = (m == 0) ? wkg : ((m == 1) ? rkg : weg);
    __shared__ float sx[16];
    __shared__ bool s_last;
    if (j < 16) sx[j] = x[p * 16 + j];
    __syncthreads();
    float acc = 0.f;
#pragma unroll
    for (int i = 0; i < 16; i++)
        acc += sx[i] * W[(p * 16 + i) * E + j];
    g_kpart[(m * PPARTS + p) * E + j] = acc;

    // last-block-done reduction
    __threadfence();
    __syncthreads();
    if (j == 0) s_last = (atomicAdd(&g_done, 1u) == 95u);
    __syncthreads();
    if (s_last) {
        float s0 = 0.f, s1 = 0.f, s2 = 0.f;
#pragma unroll
        for (int q = 0; q < PPARTS; q++) {
            s0 += g_kpart[(0 * PPARTS + q) * E + j];
            s1 += g_kpart[(1 * PPARTS + q) * E + j];
            s2 += g_kpart[(2 * PPARTS + q) * E + j];
        }
        g_wkey[j] = s0;
        g_rkey[j] = s1;
        g_erase[j] = s2;
        if (j == 0) g_done = 0u;   // reset for next graph replay
    }
}

// ============================================================
// K2 k_main: single pass over memory (256 MB), work-stealing.
// One warp processes 4-row contiguous chunks grabbed from g_next.
// Heavy math in packed f32x2 (FFMA2).
// ============================================================
#define PROCESS_ROW(V) do {                                                     \
    u64 dr2 = 0ull, dw2 = 0ull, nn2 = 0ull;                                     \
    _Pragma("unroll")                                                           \
    for (int i = 0; i < 8; i++) {                                               \
        dr2 = fma2(V[i], kr[i], dr2);                                           \
        dw2 = fma2(V[i], kw[i], dw2);                                           \
        nn2 = fma2(V[i], V[i], nn2);                                            \
    }                                                                           \
    float dr = hadd2(dr2), dw = hadd2(dw2), nn = hadd2(nn2);                    \
    _Pragma("unroll")                                                           \
    for (int o = 16; o; o >>= 1) {                                              \
        dr += __shfl_xor_sync(0xffffffffu, dr, o);                              \
        dw += __shfl_xor_sync(0xffffffffu, dw, o);                              \
        nn += __shfl_xor_sync(0xffffffffu, nn, o);                              \
    }                                                                           \
    const float inv = rsqrtf(nn);                                               \
    const float sr = dr * inv;                                                  \
    const float sw = dw * inv;                                                  \
    const float srw = sr * sw;                                                  \
    const u64 sr2 = pk2(sr, sr), srw2 = pk2(srw, srw);                          \
    _Pragma("unroll")                                                           \
    for (int i = 0; i < 8; i++) {                                               \
        acA[i] = fma2(V[i], sr2, acA[i]);                                       \
        acB[i] = fma2(V[i], srw2, acB[i]);                                      \
    }                                                                           \
    Sr += sr; Sw += sw;                                                         \
} while (0)

#define LOAD_ROW(D, rowptr) do {                                                \
    _Pragma("unroll")                                                           \
    for (int q = 0; q < 4; q++) {                                               \
        float4 t = __ldcs((rowptr) + q * 32);                                   \
        D[2 * q]     = ((u64*)&t)[0];                                           \
        D[2 * q + 1] = ((u64*)&t)[1];                                           \
    }                                                                           \
} while (0)

__global__ void __launch_bounds__(256, 2) k_main(const float* __restrict__ mem) {
    __shared__ u64 shA[8][256];   // 16 KB
    __shared__ u64 shB[8][256];   // 16 KB
    __shared__ float sS[16];

    const int tid = threadIdx.x;
    const int w = tid >> 5, l = tid & 31;

    // prologue: load final keys (4 KB, L2 broadcast) into registers
    u64 kr[8], kw[8];
    {
        const u64* rk = (const u64*)g_rkey;
        const u64* wk = (const u64*)g_wkey;
#pragma unroll
        for (int q = 0; q < 4; q++) {
            kr[2 * q]     = rk[(q * 32 + l) * 2];
            kr[2 * q + 1] = rk[(q * 32 + l) * 2 + 1];
            kw[2 * q]     = wk[(q * 32 + l) * 2];
            kw[2 * q + 1] = wk[(q * 32 + l) * 2 + 1];
        }
    }

    u64 acA[8], acB[8];
#pragma unroll
    for (int i = 0; i < 8; i++) { acA[i] = 0ull; acB[i] = 0ull; }
    float Sr = 0.f, Sw = 0.f;

    // ---- work-stealing mainloop: 4-row contiguous chunks ----
    unsigned c0 = 0, c1 = 0;
    if (l == 0) c0 = atomicAdd(&g_next, 1u);
    c0 = __shfl_sync(0xffffffffu, c0, 0);
    if (l == 0) c1 = atomicAdd(&g_next, 1u);
    c1 = __shfl_sync(0xffffffffu, c1, 0);

    u64 v[8], p[8];

    while (c0 < NCHUNK) {
        const float4* base = (const float4*)mem + (size_t)c0 * CHROWS * 128 + l;
        LOAD_ROW(v, base);
#pragma unroll
        for (int r = 0; r < CHROWS; r++) {
            if (r < CHROWS - 1) {
                LOAD_ROW(p, base + (r + 1) * 128);
            } else if (c1 < NCHUNK) {
                const float4* nb = (const float4*)mem + (size_t)c1 * CHROWS * 128 + l;
                LOAD_ROW(p, nb);
            }
            PROCESS_ROW(v);
#pragma unroll
            for (int i = 0; i < 8; i++) v[i] = p[i];
        }
        c0 = c1;
        if (l == 0) c1 = atomicAdd(&g_next, 1u);   // one chunk ahead
        c1 = __shfl_sync(0xffffffffu, c1, 0);
    }

    // per-warp accumulators -> shared slices (same packed layout)
#pragma unroll
    for (int q = 0; q < 4; q++) {
        shA[w][(q * 32 + l) * 2]     = acA[2 * q];
        shA[w][(q * 32 + l) * 2 + 1] = acA[2 * q + 1];
        shB[w][(q * 32 + l) * 2]     = acB[2 * q];
        shB[w][(q * 32 + l) * 2 + 1] = acB[2 * q + 1];
    }
    if (l == 0) { sS[w] = Sr; sS[8 + w] = Sw; }
    __syncthreads();

    const float* fA = (const float*)shA;
    const float* fB = (const float*)shB;
    for (int j = tid; j < E; j += 256) {
        float a = 0.f, b = 0.f;
#pragma unroll
        for (int k = 0; k < 8; k++) {
            a += fA[k * E + j];
            b += fB[k * E + j];
        }
        atomicAdd(&g_accA[j], a);
        atomicAdd(&g_accB[j], b);
    }
    if (tid == 0) {
        float r = 0.f, ww = 0.f;
#pragma unroll
        for (int k = 0; k < 8; k++) { r += sS[k]; ww += sS[8 + k]; }
        atomicAdd(&g_S[0], r);
        atomicAdd(&g_S[1], ww);
    }
}

// ============================================================
// K3 k_out: output GEMV, atomics into d_out (zeroed by prep).
// 128 blocks x 256 threads; block b handles rows [8b, 8b+8).
// ============================================================
__global__ void k_out(const float* __restrict__ x,
                      const float* __restrict__ post,
                      float* __restrict__ out) {
    __shared__ float sc[8];
    const int b = blockIdx.x, t = threadIdx.x;
    const int i0 = b * 8;
    if (t < 8) {
        const int i = i0 + t;
        float ci;
        if (i < E) {
            ci = x[i];
        } else {
            const int e = i - E;
            ci = (g_accA[e] - g_erase[e] * g_accB[e] * __frcp_rn(g_S[1])) *
                 __frcp_rn(g_S[0]);
        }
        sc[t] = ci;
    }
    __syncthreads();
#pragma unroll
    for (int jj = 0; jj < 2; jj++) {
        const int j = t + jj * 256;
        float acc = 0.f;
#pragma unroll
        for (int i = 0; i < 8; i++)
            acc += sc[i] * post[(i0 + i) * E + j];
        atomicAdd(&out[j], acc);
    }
}

// ============================================================
extern "C" void kernel_launch(void* const* d_in, const int* in_sizes, int n_in,
                              void* d_out, int out_size) {
    const float* x    = (const float*)d_in[0];
    const float* mem  = (const float*)d_in[1];
    const float* wkg  = (const float*)d_in[2];
    // d_in[3] = w_vect_gen: computed-but-unused in the reference (dead)
    const float* weg  = (const float*)d_in[4];
    const float* rkg  = (const float*)d_in[5];
    const float* post = (const float*)d_in[6];
    float* out = (float*)d_out;

    k_prep<<<97, 512>>>(x, wkg, weg, rkg, out);
    k_main<<<296, 256>>>(mem);
    k_out<<<128, 256>>>(x, post, out);
}